// round 15
// baseline (speedup 1.0000x reference)
#include <cuda_runtime.h>
#include <cuda_bf16.h>
#include <cstdint>

#define MEM_DIM 1024
#define N_CHILD 16384
#define TM 128
#define TN 128
#define TK 32                    // f32 per K chunk = 128 bytes per smem row
#define NCHUNK (MEM_DIM / TK)    // 32
#define M_TILES (N_CHILD / TM)   // 128
#define N_TILES (MEM_DIM / TN)   // 8
#define STAGES 3
#define STAGE_BYTES (TM * 128 + TN * 128) // 32768 (A tile + B tile)
#define SMEM_TOTAL (STAGES * STAGE_BYTES) // 98304

// Scratch (allocation-free contract: __device__ global)
__device__ float g_scratch[(size_t)M_TILES * MEM_DIM]; // per-m-tile partial column sums

__device__ __forceinline__ uint32_t smem_u32(const void* p) {
    return (uint32_t)__cvta_generic_to_shared(p);
}

// ldmatrix of 4 8x8 b16 tiles, reinterpreted as 8x4 f32 tiles, then round to tf32.
__device__ __forceinline__ void ldmatrix_x4_tf32(uint32_t* r, uint32_t addr) {
    asm volatile("ldmatrix.sync.aligned.m8n8.x4.shared.b16 {%0,%1,%2,%3}, [%4];"
                 : "=r"(r[0]), "=r"(r[1]), "=r"(r[2]), "=r"(r[3]) : "r"(addr));
    asm volatile("cvt.rna.tf32.f32 %0, %0;" : "+r"(r[0]));
    asm volatile("cvt.rna.tf32.f32 %0, %0;" : "+r"(r[1]));
    asm volatile("cvt.rna.tf32.f32 %0, %0;" : "+r"(r[2]));
    asm volatile("cvt.rna.tf32.f32 %0, %0;" : "+r"(r[3]));
}

__device__ __forceinline__ void mma_tf32(float* c, const uint32_t* a, uint32_t b0, uint32_t b1) {
    asm volatile(
        "mma.sync.aligned.m16n8k8.row.col.f32.tf32.tf32.f32 "
        "{%0,%1,%2,%3}, {%4,%5,%6,%7}, {%8,%9}, {%0,%1,%2,%3};"
        : "+f"(c[0]), "+f"(c[1]), "+f"(c[2]), "+f"(c[3])
        : "r"(a[0]), "r"(a[1]), "r"(a[2]), "r"(a[3]), "r"(b0), "r"(b1));
}

// ---------------- kernel 1: fused GEMM + sigmoid + f*c + row reduction ----------------
// A = child_h (f32, row-major [16384,1024]); B = W_fh (f32, [n,k] row-major =>
// col-major KxN as mma row.col wants). 8 warps: 2(m) x 4(n), each computes 64x32
// via m16n8k8 tf32 fragments. TK=32 f32 = 128B smem rows (same swizzle as bf16 TK=64).
__global__ void __launch_bounds__(256, 2) gemm_kernel(const float* __restrict__ child_h,
                                                      const float* __restrict__ W_fh,
                                                      const float* __restrict__ child_c,
                                                      const float* __restrict__ b_fh) {
    extern __shared__ char smem[];
    const int tid = threadIdx.x;
    const int wid = tid >> 5;
    const int lane = tid & 31;
    const int warp_m = wid & 1;   // 0..1
    const int warp_n = wid >> 1;  // 0..3
    const int n0 = blockIdx.x * TN;
    const int m0 = blockIdx.y * TM;
    const uint32_t smem_base = smem_u32(smem);

    const char* Ag = (const char*)(child_h + (size_t)m0 * MEM_DIM);
    const char* Bg = (const char*)(W_fh + (size_t)n0 * MEM_DIM);

    float acc[4][4][4];
#pragma unroll
    for (int a = 0; a < 4; ++a)
#pragma unroll
        for (int b = 0; b < 4; ++b)
#pragma unroll
            for (int c = 0; c < 4; ++c) acc[a][b][c] = 0.0f;

    // per-thread cp.async slots: 4 A chunks + 4 B chunks of 16B per stage
    const int cp_r = tid >> 3;        // 0..31 base row
    const int cp_c = tid & 7;         // 0..7 16B chunk within the 128B row
    const uint32_t cp_sw = (uint32_t)((cp_c ^ (cp_r & 7)) * 16);

#define ISSUE_STAGE(CH)                                                                  \
    {                                                                                    \
        const int _k0b = (CH) * (TK * 4); /* 128 bytes per chunk */                      \
        uint32_t _sA = smem_base + ((CH) % STAGES) * STAGE_BYTES;                        \
        uint32_t _sB = _sA + TM * 128;                                                   \
        _Pragma("unroll") for (int i = 0; i < 4; ++i) {                                  \
            int r = cp_r + i * 32;                                                       \
            const char* src = Ag + (size_t)r * (MEM_DIM * 4) + _k0b + cp_c * 16;         \
            uint32_t dst = _sA + (uint32_t)r * 128 + cp_sw;                              \
            asm volatile("cp.async.cg.shared.global [%0], [%1], 16;" ::"r"(dst),         \
                         "l"(src));                                                      \
        }                                                                                \
        _Pragma("unroll") for (int i = 0; i < 4; ++i) {                                  \
            int r = cp_r + i * 32;                                                       \
            const char* src = Bg + (size_t)r * (MEM_DIM * 4) + _k0b + cp_c * 16;         \
            uint32_t dst = _sB + (uint32_t)r * 128 + cp_sw;                              \
            asm volatile("cp.async.cg.shared.global [%0], [%1], 16;" ::"r"(dst),         \
                         "l"(src));                                                      \
        }                                                                                \
        asm volatile("cp.async.commit_group;" ::: "memory");                             \
    }

    ISSUE_STAGE(0);
    ISSUE_STAGE(1);

    // ldmatrix lane addressing (constant per thread).
    // A x4 = {rows0-7,chunk c}{rows8-15,c}{rows0-7,c+1}{rows8-15,c+1} -> a0..a3 (tf32 m16n8k8)
    const int a_row = warp_m * 64 + (lane & 15);
    const int a_cbase = lane >> 4; // 0/1: k 16B-chunk halves of the k8 step
    // B x4 = {n0-7,c}{n0-7,c+1}{n8-15,c}{n8-15,c+1} -> {g0.b0, g0.b1, g1.b0, g1.b1}
    const int b_row = warp_n * 32 + ((lane >> 4) << 3) + (lane & 7);
    const int b_cbase = (lane >> 3) & 1;

    for (int ch = 0; ch < NCHUNK; ++ch) {
        if (ch < NCHUNK - 1) {
            asm volatile("cp.async.wait_group 1;" ::: "memory");
        } else {
            asm volatile("cp.async.wait_group 0;" ::: "memory");
        }
        __syncthreads();
        if (ch + 2 < NCHUNK) ISSUE_STAGE(ch + 2);

        uint32_t sA = smem_base + (ch % STAGES) * STAGE_BYTES;
        uint32_t sB = sA + TM * 128;
#pragma unroll
        for (int ks = 0; ks < 4; ++ks) { // 4 x k8 per 32-f32 chunk
            uint32_t afrag[4][4];
#pragma unroll
            for (int mf = 0; mf < 4; ++mf) {
                int row = a_row + mf * 16;
                uint32_t addr = sA + (uint32_t)row * 128 +
                                (uint32_t)(((ks * 2 + a_cbase) ^ (row & 7)) << 4);
                ldmatrix_x4_tf32(afrag[mf], addr);
            }
            uint32_t bfrag[2][4];
#pragma unroll
            for (int np = 0; np < 2; ++np) {
                int row = b_row + np * 16;
                uint32_t addr = sB + (uint32_t)row * 128 +
                                (uint32_t)(((ks * 2 + b_cbase) ^ (row & 7)) << 4);
                ldmatrix_x4_tf32(bfrag[np], addr);
            }
#pragma unroll
            for (int mf = 0; mf < 4; ++mf)
#pragma unroll
                for (int nf = 0; nf < 4; ++nf)
                    mma_tf32(acc[mf][nf], afrag[mf], bfrag[nf >> 1][(nf & 1) * 2],
                             bfrag[nf >> 1][(nf & 1) * 2 + 1]);
        }
    }
#undef ISSUE_STAGE

    // ---- fused epilogue: sigmoid(pre + b) * child_c, column sums over 128 rows ----
    const int g = lane >> 2;  // 0..7 row group
    const int q = lane & 3;   // col pair selector
    float bq[8];
#pragma unroll
    for (int nf = 0; nf < 4; ++nf) {
        bq[nf * 2 + 0] = __ldg(b_fh + n0 + warp_n * 32 + nf * 8 + 2 * q);
        bq[nf * 2 + 1] = __ldg(b_fh + n0 + warp_n * 32 + nf * 8 + 2 * q + 1);
    }
    float csum[8];
#pragma unroll
    for (int i = 0; i < 8; ++i) csum[i] = 0.0f;

#pragma unroll
    for (int mf = 0; mf < 4; ++mf) {
#pragma unroll
        for (int rr = 0; rr < 2; ++rr) {
            const int row = m0 + warp_m * 64 + mf * 16 + g + rr * 8;
            const float* ccrow = child_c + (size_t)row * MEM_DIM + n0 + warp_n * 32;
#pragma unroll
            for (int nf = 0; nf < 4; ++nf) {
                float2 cc = *(const float2*)(ccrow + nf * 8 + 2 * q);
                float pre0 = acc[mf][nf][rr * 2 + 0] + bq[nf * 2 + 0];
                float pre1 = acc[mf][nf][rr * 2 + 1] + bq[nf * 2 + 1];
                float f0 = 1.0f / (1.0f + __expf(-pre0));
                float f1 = 1.0f / (1.0f + __expf(-pre1));
                csum[nf * 2 + 0] += f0 * cc.x;
                csum[nf * 2 + 1] += f1 * cc.y;
            }
        }
    }
    // reduce the 8 lanes sharing the same q (lanes q, q+4, ..., q+28)
#pragma unroll
    for (int i = 0; i < 8; ++i) {
        csum[i] += __shfl_xor_sync(0xFFFFFFFFu, csum[i], 4);
        csum[i] += __shfl_xor_sync(0xFFFFFFFFu, csum[i], 8);
        csum[i] += __shfl_xor_sync(0xFFFFFFFFu, csum[i], 16);
    }
    __syncthreads(); // mainloop smem reads done -> safe to reuse smem
    float* s_part = (float*)smem; // [2 warp_m][4 warp_n][32]
    if (lane < 4) {
#pragma unroll
        for (int nf = 0; nf < 4; ++nf) {
            s_part[(warp_m * 4 + warp_n) * 32 + nf * 8 + 2 * lane + 0] = csum[nf * 2 + 0];
            s_part[(warp_m * 4 + warp_n) * 32 + nf * 8 + 2 * lane + 1] = csum[nf * 2 + 1];
        }
    }
    __syncthreads();
    if (tid < TN) {
        int wn = tid >> 5, col = tid & 31;
        float tot = s_part[(0 * 4 + wn) * 32 + col] + s_part[(1 * 4 + wn) * 32 + col];
        g_scratch[(size_t)blockIdx.y * MEM_DIM + n0 + tid] = tot;
    }
}

// ---------------- kernel 2: gate mat-vecs + final reduction ----------------
__global__ void __launch_bounds__(128) finalize_kernel(
    const float* __restrict__ hs,
    const float* __restrict__ W_ih, const float* __restrict__ b_ih,
    const float* __restrict__ W_uh, const float* __restrict__ b_uh,
    const float* __restrict__ W_oh, const float* __restrict__ b_oh,
    float* __restrict__ out) {
    const int j = blockIdx.x;
    const int tid = threadIdx.x;
    const int wid = tid >> 5, lane = tid & 31;
    float pi = 0.f, pu = 0.f, po = 0.f;
    const float* wi = W_ih + (size_t)j * MEM_DIM;
    const float* wu = W_uh + (size_t)j * MEM_DIM;
    const float* wo = W_oh + (size_t)j * MEM_DIM;
#pragma unroll 4
    for (int k = tid; k < MEM_DIM; k += 128) {
        float h = hs[k];
        pi += wi[k] * h;
        pu += wu[k] * h;
        po += wo[k] * h;
    }
    float ps = g_scratch[(size_t)tid * MEM_DIM + j]; // 128 m-tile partials
#pragma unroll
    for (int off = 16; off > 0; off >>= 1) {
        pi += __shfl_xor_sync(0xFFFFFFFFu, pi, off);
        pu += __shfl_xor_sync(0xFFFFFFFFu, pu, off);
        po += __shfl_xor_sync(0xFFFFFFFFu, po, off);
        ps += __shfl_xor_sync(0xFFFFFFFFu, ps, off);
    }
    __shared__ float red[4][4];
    if (lane == 0) {
        red[0][wid] = pi; red[1][wid] = pu; red[2][wid] = po; red[3][wid] = ps;
    }
    __syncthreads();
    if (tid == 0) {
        float si = red[0][0] + red[0][1] + red[0][2] + red[0][3] + b_ih[j];
        float su = red[1][0] + red[1][1] + red[1][2] + red[1][3] + b_uh[j];
        float so = red[2][0] + red[2][1] + red[2][2] + red[2][3] + b_oh[j];
        float ss = red[3][0] + red[3][1] + red[3][2] + red[3][3];
        float ig = 1.f / (1.f + expf(-si));
        float og = 1.f / (1.f + expf(-so));
        float ug = tanhf(su);
        float c = ig * ug + ss;
        out[j] = c;
        out[MEM_DIM + j] = og * tanhf(c);
    }
}

// ---------------- launch ----------------
extern "C" void kernel_launch(void* const* d_in, const int* in_sizes, int n_in,
                              void* d_out, int out_size) {
    const float* child_c     = (const float*)d_in[0];
    const float* child_h     = (const float*)d_in[1];
    const float* child_h_sum = (const float*)d_in[2];
    const float* W_ih        = (const float*)d_in[3];
    const float* b_ih        = (const float*)d_in[4];
    const float* W_fh        = (const float*)d_in[5];
    const float* b_fh        = (const float*)d_in[6];
    const float* W_uh        = (const float*)d_in[7];
    const float* b_uh        = (const float*)d_in[8];
    const float* W_oh        = (const float*)d_in[9];
    const float* b_oh        = (const float*)d_in[10];
    float* out = (float*)d_out;

    (void)in_sizes; (void)n_in; (void)out_size;

    cudaFuncSetAttribute(gemm_kernel, cudaFuncAttributeMaxDynamicSharedMemorySize,
                         SMEM_TOTAL);

    gemm_kernel<<<dim3(N_TILES, M_TILES), 256, SMEM_TOTAL>>>(child_h, W_fh, child_c, b_fh);
    finalize_kernel<<<MEM_DIM, 128>>>(child_h_sum, W_ih, b_ih, W_uh, b_uh, W_oh, b_oh, out);
}

// round 16
// speedup vs baseline: 1.0038x; 1.0038x over previous
#include <cuda_runtime.h>
#include <cuda_bf16.h>
#include <cstdint>

#define MEM_DIM 1024
#define N_CHILD 16384
#define TM 128
#define TN 128
#define TK 32                    // f32 per K chunk = 128 bytes per smem row
#define NCHUNK (MEM_DIM / TK)    // 32
#define M_TILES (N_CHILD / TM)   // 128
#define N_TILES (MEM_DIM / TN)   // 8
#define STAGES 3
#define STAGE_BYTES (TM * 128 + TN * 128) // 32768 (A tile + B tile)
#define SMEM_TOTAL (STAGES * STAGE_BYTES) // 98304

// Scratch (allocation-free contract: __device__ global)
__device__ float g_scratch[(size_t)M_TILES * MEM_DIM]; // per-m-tile partial column sums

__device__ __forceinline__ uint32_t smem_u32(const void* p) {
    return (uint32_t)__cvta_generic_to_shared(p);
}

// ldmatrix of 4 8x8 b16 tiles, reinterpreted as 8x4 f32 tiles, then round to tf32.
__device__ __forceinline__ void ldmatrix_x4_tf32(uint32_t* r, uint32_t addr) {
    asm volatile("ldmatrix.sync.aligned.m8n8.x4.shared.b16 {%0,%1,%2,%3}, [%4];"
                 : "=r"(r[0]), "=r"(r[1]), "=r"(r[2]), "=r"(r[3]) : "r"(addr));
    asm volatile("cvt.rna.tf32.f32 %0, %0;" : "+r"(r[0]));
    asm volatile("cvt.rna.tf32.f32 %0, %0;" : "+r"(r[1]));
    asm volatile("cvt.rna.tf32.f32 %0, %0;" : "+r"(r[2]));
    asm volatile("cvt.rna.tf32.f32 %0, %0;" : "+r"(r[3]));
}

__device__ __forceinline__ void mma_tf32(float* c, const uint32_t* a, uint32_t b0, uint32_t b1) {
    asm volatile(
        "mma.sync.aligned.m16n8k8.row.col.f32.tf32.tf32.f32 "
        "{%0,%1,%2,%3}, {%4,%5,%6,%7}, {%8,%9}, {%0,%1,%2,%3};"
        : "+f"(c[0]), "+f"(c[1]), "+f"(c[2]), "+f"(c[3])
        : "r"(a[0]), "r"(a[1]), "r"(a[2]), "r"(a[3]), "r"(b0), "r"(b1));
}

// ---------------- kernel 1: fused GEMM + sigmoid + f*c + row reduction ----------------
// A = child_h (f32, row-major [16384,1024]); B = W_fh (f32, [n,k] row-major =>
// col-major KxN as mma row.col wants). 8 warps: 2(m) x 4(n), each computes 64x32
// via m16n8k8 tf32 fragments. TK=32 f32 = 128B smem rows (same swizzle as bf16 TK=64).
__global__ void __launch_bounds__(256, 2) gemm_kernel(const float* __restrict__ child_h,
                                                      const float* __restrict__ W_fh,
                                                      const float* __restrict__ child_c,
                                                      const float* __restrict__ b_fh) {
    extern __shared__ char smem[];
    const int tid = threadIdx.x;
    const int wid = tid >> 5;
    const int lane = tid & 31;
    const int warp_m = wid & 1;   // 0..1
    const int warp_n = wid >> 1;  // 0..3
    const int n0 = blockIdx.x * TN;
    const int m0 = blockIdx.y * TM;
    const uint32_t smem_base = smem_u32(smem);

    const char* Ag = (const char*)(child_h + (size_t)m0 * MEM_DIM);
    const char* Bg = (const char*)(W_fh + (size_t)n0 * MEM_DIM);

    float acc[4][4][4];
#pragma unroll
    for (int a = 0; a < 4; ++a)
#pragma unroll
        for (int b = 0; b < 4; ++b)
#pragma unroll
            for (int c = 0; c < 4; ++c) acc[a][b][c] = 0.0f;

    // per-thread cp.async slots: 4 A chunks + 4 B chunks of 16B per stage
    const int cp_r = tid >> 3;        // 0..31 base row
    const int cp_c = tid & 7;         // 0..7 16B chunk within the 128B row
    const uint32_t cp_sw = (uint32_t)((cp_c ^ (cp_r & 7)) * 16);

#define ISSUE_STAGE(CH)                                                                  \
    {                                                                                    \
        const int _k0b = (CH) * (TK * 4); /* 128 bytes per chunk */                      \
        uint32_t _sA = smem_base + ((CH) % STAGES) * STAGE_BYTES;                        \
        uint32_t _sB = _sA + TM * 128;                                                   \
        _Pragma("unroll") for (int i = 0; i < 4; ++i) {                                  \
            int r = cp_r + i * 32;                                                       \
            const char* src = Ag + (size_t)r * (MEM_DIM * 4) + _k0b + cp_c * 16;         \
            uint32_t dst = _sA + (uint32_t)r * 128 + cp_sw;                              \
            asm volatile("cp.async.cg.shared.global [%0], [%1], 16;" ::"r"(dst),         \
                         "l"(src));                                                      \
        }                                                                                \
        _Pragma("unroll") for (int i = 0; i < 4; ++i) {                                  \
            int r = cp_r + i * 32;                                                       \
            const char* src = Bg + (size_t)r * (MEM_DIM * 4) + _k0b + cp_c * 16;         \
            uint32_t dst = _sB + (uint32_t)r * 128 + cp_sw;                              \
            asm volatile("cp.async.cg.shared.global [%0], [%1], 16;" ::"r"(dst),         \
                         "l"(src));                                                      \
        }                                                                                \
        asm volatile("cp.async.commit_group;" ::: "memory");                             \
    }

    ISSUE_STAGE(0);
    ISSUE_STAGE(1);

    // ldmatrix lane addressing (constant per thread).
    // A x4 = {rows0-7,chunk c}{rows8-15,c}{rows0-7,c+1}{rows8-15,c+1} -> a0..a3 (tf32 m16n8k8)
    const int a_row = warp_m * 64 + (lane & 15);
    const int a_cbase = lane >> 4; // 0/1: k 16B-chunk halves of the k8 step
    // B x4 = {n0-7,c}{n0-7,c+1}{n8-15,c}{n8-15,c+1} -> {g0.b0, g0.b1, g1.b0, g1.b1}
    const int b_row = warp_n * 32 + ((lane >> 4) << 3) + (lane & 7);
    const int b_cbase = (lane >> 3) & 1;

    for (int ch = 0; ch < NCHUNK; ++ch) {
        if (ch < NCHUNK - 1) {
            asm volatile("cp.async.wait_group 1;" ::: "memory");
        } else {
            asm volatile("cp.async.wait_group 0;" ::: "memory");
        }
        __syncthreads();
        if (ch + 2 < NCHUNK) ISSUE_STAGE(ch + 2);

        uint32_t sA = smem_base + (ch % STAGES) * STAGE_BYTES;
        uint32_t sB = sA + TM * 128;
#pragma unroll
        for (int ks = 0; ks < 4; ++ks) { // 4 x k8 per 32-f32 chunk
            uint32_t afrag[4][4];
#pragma unroll
            for (int mf = 0; mf < 4; ++mf) {
                int row = a_row + mf * 16;
                uint32_t addr = sA + (uint32_t)row * 128 +
                                (uint32_t)(((ks * 2 + a_cbase) ^ (row & 7)) << 4);
                ldmatrix_x4_tf32(afrag[mf], addr);
            }
            uint32_t bfrag[2][4];
#pragma unroll
            for (int np = 0; np < 2; ++np) {
                int row = b_row + np * 16;
                uint32_t addr = sB + (uint32_t)row * 128 +
                                (uint32_t)(((ks * 2 + b_cbase) ^ (row & 7)) << 4);
                ldmatrix_x4_tf32(bfrag[np], addr);
            }
#pragma unroll
            for (int mf = 0; mf < 4; ++mf)
#pragma unroll
                for (int nf = 0; nf < 4; ++nf)
                    mma_tf32(acc[mf][nf], afrag[mf], bfrag[nf >> 1][(nf & 1) * 2],
                             bfrag[nf >> 1][(nf & 1) * 2 + 1]);
        }
    }
#undef ISSUE_STAGE

    // ---- fused epilogue: sigmoid(pre + b) * child_c, column sums over 128 rows ----
    const int g = lane >> 2;  // 0..7 row group
    const int q = lane & 3;   // col pair selector
    float bq[8];
#pragma unroll
    for (int nf = 0; nf < 4; ++nf) {
        bq[nf * 2 + 0] = __ldg(b_fh + n0 + warp_n * 32 + nf * 8 + 2 * q);
        bq[nf * 2 + 1] = __ldg(b_fh + n0 + warp_n * 32 + nf * 8 + 2 * q + 1);
    }
    float csum[8];
#pragma unroll
    for (int i = 0; i < 8; ++i) csum[i] = 0.0f;

#pragma unroll
    for (int mf = 0; mf < 4; ++mf) {
#pragma unroll
        for (int rr = 0; rr < 2; ++rr) {
            const int row = m0 + warp_m * 64 + mf * 16 + g + rr * 8;
            const float* ccrow = child_c + (size_t)row * MEM_DIM + n0 + warp_n * 32;
#pragma unroll
            for (int nf = 0; nf < 4; ++nf) {
                float2 cc = *(const float2*)(ccrow + nf * 8 + 2 * q);
                float pre0 = acc[mf][nf][rr * 2 + 0] + bq[nf * 2 + 0];
                float pre1 = acc[mf][nf][rr * 2 + 1] + bq[nf * 2 + 1];
                float f0 = 1.0f / (1.0f + __expf(-pre0));
                float f1 = 1.0f / (1.0f + __expf(-pre1));
                csum[nf * 2 + 0] += f0 * cc.x;
                csum[nf * 2 + 1] += f1 * cc.y;
            }
        }
    }
    // reduce the 8 lanes sharing the same q (lanes q, q+4, ..., q+28)
#pragma unroll
    for (int i = 0; i < 8; ++i) {
        csum[i] += __shfl_xor_sync(0xFFFFFFFFu, csum[i], 4);
        csum[i] += __shfl_xor_sync(0xFFFFFFFFu, csum[i], 8);
        csum[i] += __shfl_xor_sync(0xFFFFFFFFu, csum[i], 16);
    }
    __syncthreads(); // mainloop smem reads done -> safe to reuse smem
    float* s_part = (float*)smem; // [2 warp_m][4 warp_n][32]
    if (lane < 4) {
#pragma unroll
        for (int nf = 0; nf < 4; ++nf) {
            s_part[(warp_m * 4 + warp_n) * 32 + nf * 8 + 2 * lane + 0] = csum[nf * 2 + 0];
            s_part[(warp_m * 4 + warp_n) * 32 + nf * 8 + 2 * lane + 1] = csum[nf * 2 + 1];
        }
    }
    __syncthreads();
    if (tid < TN) {
        int wn = tid >> 5, col = tid & 31;
        float tot = s_part[(0 * 4 + wn) * 32 + col] + s_part[(1 * 4 + wn) * 32 + col];
        g_scratch[(size_t)blockIdx.y * MEM_DIM + n0 + tid] = tot;
    }
}

// ---------------- kernel 2: gate mat-vecs + final reduction ----------------
__global__ void __launch_bounds__(128) finalize_kernel(
    const float* __restrict__ hs,
    const float* __restrict__ W_ih, const float* __restrict__ b_ih,
    const float* __restrict__ W_uh, const float* __restrict__ b_uh,
    const float* __restrict__ W_oh, const float* __restrict__ b_oh,
    float* __restrict__ out) {
    const int j = blockIdx.x;
    const int tid = threadIdx.x;
    const int wid = tid >> 5, lane = tid & 31;
    float pi = 0.f, pu = 0.f, po = 0.f;
    const float* wi = W_ih + (size_t)j * MEM_DIM;
    const float* wu = W_uh + (size_t)j * MEM_DIM;
    const float* wo = W_oh + (size_t)j * MEM_DIM;
#pragma unroll 4
    for (int k = tid; k < MEM_DIM; k += 128) {
        float h = hs[k];
        pi += wi[k] * h;
        pu += wu[k] * h;
        po += wo[k] * h;
    }
    float ps = g_scratch[(size_t)tid * MEM_DIM + j]; // 128 m-tile partials
#pragma unroll
    for (int off = 16; off > 0; off >>= 1) {
        pi += __shfl_xor_sync(0xFFFFFFFFu, pi, off);
        pu += __shfl_xor_sync(0xFFFFFFFFu, pu, off);
        po += __shfl_xor_sync(0xFFFFFFFFu, po, off);
        ps += __shfl_xor_sync(0xFFFFFFFFu, ps, off);
    }
    __shared__ float red[4][4];
    if (lane == 0) {
        red[0][wid] = pi; red[1][wid] = pu; red[2][wid] = po; red[3][wid] = ps;
    }
    __syncthreads();
    if (tid == 0) {
        float si = red[0][0] + red[0][1] + red[0][2] + red[0][3] + b_ih[j];
        float su = red[1][0] + red[1][1] + red[1][2] + red[1][3] + b_uh[j];
        float so = red[2][0] + red[2][1] + red[2][2] + red[2][3] + b_oh[j];
        float ss = red[3][0] + red[3][1] + red[3][2] + red[3][3];
        float ig = 1.f / (1.f + expf(-si));
        float og = 1.f / (1.f + expf(-so));
        float ug = tanhf(su);
        float c = ig * ug + ss;
        out[j] = c;
        out[MEM_DIM + j] = og * tanhf(c);
    }
}

// ---------------- launch ----------------
extern "C" void kernel_launch(void* const* d_in, const int* in_sizes, int n_in,
                              void* d_out, int out_size) {
    const float* child_c     = (const float*)d_in[0];
    const float* child_h     = (const float*)d_in[1];
    const float* child_h_sum = (const float*)d_in[2];
    const float* W_ih        = (const float*)d_in[3];
    const float* b_ih        = (const float*)d_in[4];
    const float* W_fh        = (const float*)d_in[5];
    const float* b_fh        = (const float*)d_in[6];
    const float* W_uh        = (const float*)d_in[7];
    const float* b_uh        = (const float*)d_in[8];
    const float* W_oh        = (const float*)d_in[9];
    const float* b_oh        = (const float*)d_in[10];
    float* out = (float*)d_out;

    (void)in_sizes; (void)n_in; (void)out_size;

    cudaFuncSetAttribute(gemm_kernel, cudaFuncAttributeMaxDynamicSharedMemorySize,
                         SMEM_TOTAL);

    gemm_kernel<<<dim3(N_TILES, M_TILES), 256, SMEM_TOTAL>>>(child_h, W_fh, child_c, b_fh);
    finalize_kernel<<<MEM_DIM, 128>>>(child_h_sum, W_ih, b_ih, W_uh, b_uh, W_oh, b_oh, out);
}